// round 16
// baseline (speedup 1.0000x reference)
#include <cuda_runtime.h>
#include <cstdint>
#include <cstddef>

#define N_   50000
#define K_   48
#define C_   128
#define H_   8
#define D_   16
#define FF_  256
#define OUT_ 128
#define MT   32
#define S_   36
#define NBLK ((N_ + MT - 1) / MT)

typedef unsigned long long u64;

// ---- f32x2 packed helpers (Blackwell sm_100+) ----
__device__ __forceinline__ u64 pk2(float w) {
    u64 r; asm("mov.b64 %0,{%1,%1};" : "=l"(r) : "f"(w)); return r;
}
__device__ __forceinline__ void f2(u64& d, u64 a, u64 b) {
    asm("fma.rn.f32x2 %0,%1,%2,%0;" : "+l"(d) : "l"(a), "l"(b));
}
__device__ __forceinline__ float2 up2(u64 a) {
    float2 r; asm("mov.b64 {%0,%1},%2;" : "=f"(r.x), "=f"(r.y) : "l"(a)); return r;
}

// ---------------- device scratch ----------------
__device__ float g_QK[(size_t)N_ * H_ * C_];
__device__ float g_QB[(size_t)N_ * H_];
__device__ float g_CTXF[(size_t)N_ * H_ * C_];
__device__ float g_wqT[C_ * C_];
__device__ float g_wvT[C_ * C_];
__device__ float g_opT[C_ * C_];
__device__ float g_ff1T[C_ * FF_];
__device__ float g_ff2T[FF_ * C_];
__device__ float g_outT[C_ * OUT_];
__device__ int   g_mask_is_byte;

// ---------------- weight transposes + mask dtype detect (block 0) ----------------
__global__ void kPrep(const float* __restrict__ ipw, const float* __restrict__ opw,
                      const float* __restrict__ f1w, const float* __restrict__ f2w,
                      const float* __restrict__ ow, const int* __restrict__ km) {
    int i = blockIdx.x * blockDim.x + threadIdx.x;
    if (i < 16384) {
        int e = i >> 7, c = i & 127;
        g_wqT[c * C_ + e] = ipw[e * C_ + c];
    } else if (i < 32768) {
        int j = i - 16384; int e = j >> 7, c = j & 127;
        g_wvT[c * C_ + e] = ipw[(2 * C_ + e) * C_ + c];
    } else if (i < 49152) {
        int j = i - 32768; int e = j >> 7, c = j & 127;
        g_opT[c * C_ + e] = opw[e * C_ + c];
    } else if (i < 81920) {
        int j = i - 49152; int f = j >> 7, c = j & 127;
        g_ff1T[c * FF_ + f] = f1w[f * C_ + c];
    } else if (i < 114688) {
        int j = i - 81920; int e = j >> 8, f = j & 255;
        g_ff2T[f * C_ + e] = f2w[e * FF_ + f];
    } else if (i < 131072) {
        int j = i - 114688; int o = j >> 7, c = j & 127;
        g_outT[c * OUT_ + o] = ow[o * C_ + c];
    }
    if (blockIdx.x == 0) {
        __shared__ int s;
        if (threadIdx.x == 0) s = 0;
        __syncthreads();
        int bad = 0;
        for (int ii = threadIdx.x; ii < 4096; ii += 256)
            if (((unsigned)km[ii]) > 1u) bad = 1;
        if (bad) atomicOr(&s, 1);
        __syncthreads();
        if (threadIdx.x == 0) g_mask_is_byte = s;
    }
}

// ---- tiled-GEMM helpers: thread covers ch = ch0..ch0+3, m = mg8..mg8+7 ----
#define ZACC(A) do { _Pragma("unroll") for (int j_=0;j_<4;j_++) { \
    _Pragma("unroll") for (int p_=0;p_<4;p_++) (A)[j_][p_] = 0; } } while (0)

#define G2STEP(BUF, ROW, W4, ACC) do {                                          \
    ulonglong2 x01_ = *(const ulonglong2*)&(BUF)[(ROW)*S_ + mg8];               \
    ulonglong2 x23_ = *(const ulonglong2*)&(BUF)[(ROW)*S_ + mg8 + 4];           \
    u64 w0_=pk2((W4).x), w1_=pk2((W4).y), w2_=pk2((W4).z), w3_=pk2((W4).w);     \
    f2((ACC)[0][0],x01_.x,w0_); f2((ACC)[0][1],x01_.y,w0_);                     \
    f2((ACC)[0][2],x23_.x,w0_); f2((ACC)[0][3],x23_.y,w0_);                     \
    f2((ACC)[1][0],x01_.x,w1_); f2((ACC)[1][1],x01_.y,w1_);                     \
    f2((ACC)[1][2],x23_.x,w1_); f2((ACC)[1][3],x23_.y,w1_);                     \
    f2((ACC)[2][0],x01_.x,w2_); f2((ACC)[2][1],x01_.y,w2_);                     \
    f2((ACC)[2][2],x23_.x,w2_); f2((ACC)[2][3],x23_.y,w2_);                     \
    f2((ACC)[3][0],x01_.x,w3_); f2((ACC)[3][1],x01_.y,w3_);                     \
    f2((ACC)[3][2],x23_.x,w3_); f2((ACC)[3][3],x23_.y,w3_);                     \
} while (0)

#define STORE4(BUF, ACC, B4PTR, RELU) do {                                      \
    float4 b4_ = (B4PTR)[og];                                                   \
    float bj_[4] = {b4_.x, b4_.y, b4_.z, b4_.w};                                \
    _Pragma("unroll") for (int j_=0;j_<4;j_++) {                                \
      _Pragma("unroll") for (int p_=0;p_<4;p_++) {                              \
        float2 s_ = up2((ACC)[j_][p_]);                                         \
        s_.x += bj_[j_]; s_.y += bj_[j_];                                       \
        if (RELU) { s_.x = fmaxf(s_.x, 0.f); s_.y = fmaxf(s_.y, 0.f); }         \
        *(float2*)&(BUF)[(ch0+j_)*S_ + mg8 + 2*p_] = s_;                        \
      } }                                                                       \
} while (0)

// vectorized LN apply: x = (x - mean)*rstd*g + b over m = 0..31 (float4)
#define LNAPPLY(BUF, GV, BV) do {                                               \
    float g_ = (GV), b_ = (BV);                                                 \
    _Pragma("unroll")                                                           \
    for (int m4_ = 0; m4_ < 8; m4_++) {                                         \
        float4 x_  = *(float4*)&(BUF)[t * S_ + 4*m4_];                          \
        float4 mn_ = *(const float4*)&mean_s[4*m4_];                            \
        float4 rs_ = *(const float4*)&rstd_s[4*m4_];                            \
        x_.x = (x_.x - mn_.x) * rs_.x * g_ + b_;                                \
        x_.y = (x_.y - mn_.y) * rs_.y * g_ + b_;                                \
        x_.z = (x_.z - mn_.z) * rs_.z * g_ + b_;                                \
        x_.w = (x_.w - mn_.w) * rs_.w * g_ + b_;                                \
        *(float4*)&(BUF)[t * S_ + 4*m4_] = x_;                                  \
    } } while (0)

// ---------------- kernel A ----------------
__global__ void __launch_bounds__(128) kA(const float* __restrict__ vf,
                                          const float* __restrict__ ipw,
                                          const float* __restrict__ ipb) {
    __shared__ float vsT[C_ * S_];
    __shared__ float QsT[C_ * S_];
    int t = threadIdx.x;
    int n0 = blockIdx.x * MT;
    int mg = t & 3, og = t >> 2;
    int mg8 = mg * 8, ch0 = og * 4;

    #pragma unroll
    for (int m4 = 0; m4 < 8; m4++) {
        float a[4];
        #pragma unroll
        for (int j = 0; j < 4; j++) {
            int n = n0 + 4*m4 + j; if (n >= N_) n = N_ - 1;
            a[j] = vf[(size_t)n * C_ + t];
        }
        *(float4*)&vsT[t * S_ + 4*m4] = make_float4(a[0], a[1], a[2], a[3]);
    }
    __syncthreads();

    u64 acc[4][4];
    ZACC(acc);
    for (int c = 0; c < C_; c++) {
        float4 w4 = *(const float4*)&g_wqT[c * C_ + ch0];
        G2STEP(vsT, c, w4, acc);
    }
    STORE4(QsT, acc, (const float4*)ipb, false);
    __syncthreads();

    for (int h = 0; h < H_; h++) {
        ZACC(acc);
        #pragma unroll
        for (int d = 0; d < D_; d++) {
            int e = h * D_ + d;
            float4 w4 = *(const float4*)&ipw[(size_t)(C_ + e) * C_ + ch0];
            G2STEP(QsT, e, w4, acc);
        }
        #pragma unroll
        for (int j = 0; j < 4; j++)
            #pragma unroll
            for (int p = 0; p < 4; p++) {
                float2 s = up2(acc[j][p]);
                int m0 = mg8 + 2*p;
                int na = n0 + m0, nb = n0 + m0 + 1;
                if (na < N_) g_QK[(size_t)na * (H_*C_) + h * C_ + ch0 + j] = s.x;
                if (nb < N_) g_QK[(size_t)nb * (H_*C_) + h * C_ + ch0 + j] = s.y;
            }
    }
    if (t < MT) {
        int n = n0 + t;
        if (n < N_) {
            for (int h = 0; h < H_; h++) {
                float s = 0.f;
                for (int d = 0; d < D_; d++) {
                    int e = h * D_ + d;
                    s = fmaf(QsT[e * S_ + t], ipb[C_ + e], s);
                }
                g_QB[(size_t)n * H_ + h] = s;
            }
        }
    }
}

// ---------------- kernel B: 24-lane Tk=4/Th=4 scores + 4-warp softmax + 2-warp ctxfeat ----------------
__global__ void __launch_bounds__(128) kB(const float* __restrict__ vf,
                                          const float* __restrict__ coords,
                                          const int* __restrict__ kidx,
                                          const void* __restrict__ kmask,
                                          const float* __restrict__ kpw,
                                          const float* __restrict__ kpb) {
    __shared__ float4 kf4[K_ * 33];
    __shared__ float4 qk4[H_ * 33];
    __shared__ __align__(16) float attnS[K_ * 8];      // [k*8 + h]
    __shared__ int   idxs[K_];
    __shared__ float relx[K_], rely[K_], relz[K_];
    __shared__ float qb_s[H_];
    __shared__ unsigned char msk[K_];

    int t = threadIdx.x;
    int n = blockIdx.x;
    int isbyte = g_mask_is_byte;

    if (t < K_) {
        int i = kidx[(size_t)n * K_ + t];
        idxs[t] = i;
        unsigned char mk;
        if (isbyte) mk = (((const unsigned char*)kmask)[(size_t)n * K_ + t] != 0);
        else        mk = (((const int*)kmask)[(size_t)n * K_ + t] != 0);
        msk[t] = mk;
        relx[t] = coords[(size_t)i * 3 + 0] - coords[(size_t)n * 3 + 0];
        rely[t] = coords[(size_t)i * 3 + 1] - coords[(size_t)n * 3 + 1];
        relz[t] = coords[(size_t)i * 3 + 2] - coords[(size_t)n * 3 + 2];
    }
    if (t < H_) qb_s[t] = g_QB[(size_t)n * H_ + t];
    {
        int h = t >> 4, c2 = (t & 15) * 2;
        const float4* src = (const float4*)(g_QK + (size_t)n * (H_ * C_) + h * C_);
        qk4[h * 33 + c2]     = __ldg(src + c2);
        qk4[h * 33 + c2 + 1] = __ldg(src + c2 + 1);
    }

    int c4 = t & 31, q = t >> 5;
    float4 wa = __ldg((const float4*)(kpw + 12 * c4));
    float4 wb = __ldg((const float4*)(kpw + 12 * c4 + 4));
    float4 wc = __ldg((const float4*)(kpw + 12 * c4 + 8));
    float4 pb4 = __ldg((const float4*)(kpb + 4 * c4));
    __syncthreads();

    // gather + posemb: 4 channels x 12 keys per thread
    #pragma unroll
    for (int kk = 0; kk < 12; kk++) {
        int k = q * 12 + kk;
        int i = idxs[k];
        float4 v = __ldg((const float4*)(vf + (size_t)i * C_) + c4);
        float rx = relx[k], ry = rely[k], rz = relz[k];
        float p0 = fmaf(rz, wa.z, fmaf(ry, wa.y, fmaf(rx, wa.x, pb4.x)));
        float p1 = fmaf(rz, wb.y, fmaf(ry, wb.x, fmaf(rx, wa.w, pb4.y)));
        float p2 = fmaf(rz, wc.x, fmaf(ry, wb.w, fmaf(rx, wb.z, pb4.z)));
        float p3 = fmaf(rz, wc.w, fmaf(ry, wc.z, fmaf(rx, wc.y, pb4.w)));
        v.x += fmaxf(p0, 0.f); v.y += fmaxf(p1, 0.f);
        v.z += fmaxf(p2, 0.f); v.w += fmaxf(p3, 0.f);
        kf4[k * 33 + c4] = v;
    }
    __syncthreads();

    // scores: 24 lanes; lane = (g = t/12 head-quad, kp = t%12), keys {kp, +12, +24, +36}
    // per c-iter: 8 LDS.128 x 3 phases = 24 wf (vs 28 in the 32-lane Tk=3 version)
    if (t < 24) {
        int g  = t / 12;
        int kp = t - g * 12;
        u64 a[4][4];                // [kk][j]
        #pragma unroll
        for (int kk = 0; kk < 4; kk++)
            #pragma unroll
            for (int j = 0; j < 4; j++) a[kk][j] = 0;
        #pragma unroll 4
        for (int c = 0; c < 32; c++) {
            ulonglong2 f0 = *(const ulonglong2*)&kf4[kp * 33 + c];
            ulonglong2 f1 = *(const ulonglong2*)&kf4[(kp + 12) * 33 + c];
            ulonglong2 fv = *(const ulonglong2*)&kf4[(kp + 24) * 33 + c];
            ulonglong2 f3 = *(const ulonglong2*)&kf4[(kp + 36) * 33 + c];
            #pragma unroll
            for (int j = 0; j < 4; j++) {
                ulonglong2 qv = *(const ulonglong2*)&qk4[(4 * g + j) * 33 + c];
                f2(a[0][j], f0.x, qv.x); f2(a[0][j], f0.y, qv.y);
                f2(a[1][j], f1.x, qv.x); f2(a[1][j], f1.y, qv.y);
                f2(a[2][j], fv.x, qv.x); f2(a[2][j], fv.y, qv.y);
                f2(a[3][j], f3.x, qv.x); f2(a[3][j], f3.y, qv.y);
            }
        }
        #pragma unroll
        for (int kk = 0; kk < 4; kk++) {
            int k = kp + 12 * kk;
            bool mk = msk[k] != 0;
            float4 o;
            float* op = (float*)&o;
            #pragma unroll
            for (int j = 0; j < 4; j++) {
                float2 s = up2(a[kk][j]);
                float val = (s.x + s.y + qb_s[4 * g + j]) * 0.25f;
                op[j] = mk ? -1e9f : val;
            }
            *(float4*)&attnS[k * 8 + 4 * g] = o;
        }
    }
    __syncthreads();

    // softmax: warp w -> heads 2w, 2w+1
    {
        int w = t >> 5, l = t & 31;
        #pragma unroll
        for (int hh = 0; hh < 2; hh++) {
            int h = 2 * w + hh;
            float a = attnS[l * 8 + h];
            float b = (l < 16) ? attnS[(32 + l) * 8 + h] : -3.4e38f;
            float mx = fmaxf(a, b);
            #pragma unroll
            for (int o = 16; o > 0; o >>= 1) mx = fmaxf(mx, __shfl_xor_sync(0xffffffffu, mx, o));
            float ea = __expf(a - mx);
            float eb = (l < 16) ? __expf(b - mx) : 0.f;
            float sm = ea + eb;
            #pragma unroll
            for (int o = 16; o > 0; o >>= 1) sm += __shfl_xor_sync(0xffffffffu, sm, o);
            float inv = 1.f / sm;
            attnS[l * 8 + h] = ea * inv;
            if (l < 16) attnS[(32 + l) * 8 + h] = eb * inv;
        }
    }
    __syncthreads();

    // ctxfeat: 2 warps; warp w -> heads 4w..4w+3, lane -> float4 column
    if (t < 64) {
        int w = t >> 5, cc = t & 31;
        u64 A[4][2];
        #pragma unroll
        for (int j = 0; j < 4; j++) { A[j][0] = 0; A[j][1] = 0; }
        #pragma unroll 4
        for (int k = 0; k < K_; k++) {
            ulonglong2 f = *(const ulonglong2*)&kf4[k * 33 + cc];
            float4 a4 = *(const float4*)&attnS[k * 8 + 4 * w];
            u64 a0 = pk2(a4.x), a1 = pk2(a4.y), a2 = pk2(a4.z), a3 = pk2(a4.w);
            f2(A[0][0], f.x, a0); f2(A[0][1], f.y, a0);
            f2(A[1][0], f.x, a1); f2(A[1][1], f.y, a1);
            f2(A[2][0], f.x, a2); f2(A[2][1], f.y, a2);
            f2(A[3][0], f.x, a3); f2(A[3][1], f.y, a3);
        }
        float4* dst = (float4*)(g_CTXF + (size_t)n * (H_ * C_));
        #pragma unroll
        for (int j = 0; j < 4; j++) {
            float2 xy = up2(A[j][0]);
            float2 zw = up2(A[j][1]);
            dst[(4 * w + j) * 32 + cc] = make_float4(xy.x, xy.y, zw.x, zw.y);
        }
    }
}

// ---------------- kernel C (R14: vectorized elementwise phases) ----------------
__global__ void __launch_bounds__(128) kC(const float* __restrict__ vf,
                                          const float* __restrict__ ipb,
                                          const float* __restrict__ opb,
                                          const float* __restrict__ ln1g, const float* __restrict__ ln1b,
                                          const float* __restrict__ ln2g, const float* __restrict__ ln2b,
                                          const float* __restrict__ ff1b, const float* __restrict__ ff2b,
                                          const float* __restrict__ outb,
                                          const float* __restrict__ ln3g, const float* __restrict__ ln3b,
                                          float* __restrict__ out) {
    __shared__ float bufA[C_ * S_];
    __shared__ float bufC[C_ * S_];
    __shared__ __align__(16) float mean_s[MT];
    __shared__ __align__(16) float rstd_s[MT];

    int t = threadIdx.x;
    int n0 = blockIdx.x * MT;
    int mg = t & 3, og = t >> 2;
    int mg8 = mg * 8, ch0 = og * 4;

    u64 acc[4][4];
    ZACC(acc);

    // --- ctx: staged ctxfeat chunks (8 x 16 cols, sequential) ---
    int rb = (og >> 2) * 16;
    for (int ch = 0; ch < 8; ch++) {
        int c0 = ch * 16;
        __syncthreads();
        {
            int hh = t >> 4, cl = t & 15;
            #pragma unroll
            for (int m4 = 0; m4 < 8; m4++) {
                float a[4];
                #pragma unroll
                for (int j = 0; j < 4; j++) {
                    int n = n0 + 4*m4 + j; if (n >= N_) n = N_ - 1;
                    a[j] = g_CTXF[(size_t)n * (H_*C_) + hh * C_ + c0 + cl];
                }
                *(float4*)&bufC[t * S_ + 4*m4] = make_float4(a[0], a[1], a[2], a[3]);
            }
        }
        __syncthreads();
        #pragma unroll
        for (int cl = 0; cl < 16; cl++) {
            float4 w4 = *(const float4*)&g_wvT[(c0 + cl) * C_ + ch0];
            G2STEP(bufC, rb + cl, w4, acc);
        }
    }
    __syncthreads();
    STORE4(bufC, acc, (const float4*)(ipb + 2 * C_), false);
    __syncthreads();

    // --- attend ---
    ZACC(acc);
    for (int c = 0; c < C_; c++) {
        float4 w4 = *(const float4*)&g_opT[c * C_ + ch0];
        G2STEP(bufC, c, w4, acc);
    }
    __syncthreads();
    STORE4(bufA, acc, (const float4*)opb, false);
    __syncthreads();
    // residual (coalesced LDG, vectorized smem)
    #pragma unroll
    for (int m4 = 0; m4 < 8; m4++) {
        float4 x = *(float4*)&bufA[t * S_ + 4*m4];
        float r[4];
        #pragma unroll
        for (int j = 0; j < 4; j++) {
            int n = n0 + 4*m4 + j; if (n >= N_) n = N_ - 1;
            r[j] = vf[(size_t)n * C_ + t];
        }
        x.x += r[0]; x.y += r[1]; x.z += r[2]; x.w += r[3];
        *(float4*)&bufA[t * S_ + 4*m4] = x;
    }
    __syncthreads();
    if (t < MT) {
        float s = 0.f, s2 = 0.f;
        for (int c = 0; c < C_; c++) { float v = bufA[c * S_ + t]; s += v; s2 = fmaf(v, v, s2); }
        float mn = s * (1.f / C_);
        mean_s[t] = mn; rstd_s[t] = rsqrtf(s2 * (1.f / C_) - mn * mn + 1e-5f);
    }
    __syncthreads();
    LNAPPLY(bufA, ln1g[t], ln1b[t]);
    __syncthreads();

    // --- FF ---
    u64 acc2[4][4];
    ZACC(acc2);
    for (int fc = 0; fc < 2; fc++) {
        ZACC(acc);
        for (int c = 0; c < C_; c++) {
            float4 w4 = *(const float4*)&g_ff1T[c * FF_ + fc * 128 + ch0];
            G2STEP(bufA, c, w4, acc);
        }
        __syncthreads();
        STORE4(bufC, acc, (const float4*)(ff1b + fc * 128), true);
        __syncthreads();
        for (int fl = 0; fl < 128; fl++) {
            float4 w4 = *(const float4*)&g_ff2T[(size_t)(fc * 128 + fl) * C_ + ch0];
            G2STEP(bufC, fl, w4, acc2);
        }
    }
    __syncthreads();
    STORE4(bufC, acc2, (const float4*)ff2b, false);
    __syncthreads();
    // x2 = x1 + ff (vectorized)
    #pragma unroll
    for (int m4 = 0; m4 < 8; m4++) {
        float4 x = *(float4*)&bufA[t * S_ + 4*m4];
        float4 y = *(const float4*)&bufC[t * S_ + 4*m4];
        x.x += y.x; x.y += y.y; x.z += y.z; x.w += y.w;
        *(float4*)&bufA[t * S_ + 4*m4] = x;
    }
    __syncthreads();
    if (t < MT) {
        float s = 0.f, s2 = 0.f;
        for (int c = 0; c < C_; c++) { float v = bufA[c * S_ + t]; s += v; s2 = fmaf(v, v, s2); }
        float mn = s * (1.f / C_);
        mean_s[t] = mn; rstd_s[t] = rsqrtf(s2 * (1.f / C_) - mn * mn + 1e-5f);
    }
    __syncthreads();
    LNAPPLY(bufA, ln2g[t], ln2b[t]);
    __syncthreads();

    // --- out projection ---
    ZACC(acc);
    for (int c = 0; c < C_; c++) {
        float4 w4 = *(const float4*)&g_outT[c * OUT_ + ch0];
        G2STEP(bufA, c, w4, acc);
    }
    __syncthreads();
    STORE4(bufC, acc, (const float4*)outb, false);
    __syncthreads();
    if (t < MT) {
        float s = 0.f, s2 = 0.f;
        for (int c = 0; c < OUT_; c++) { float v = bufC[c * S_ + t]; s += v; s2 = fmaf(v, v, s2); }
        float mn = s * (1.f / OUT_);
        mean_s[t] = mn; rstd_s[t] = rsqrtf(s2 * (1.f / OUT_) - mn * mn + 1e-5f);
    }
    __syncthreads();
    {
        float g = ln3g[t], b = ln3b[t];
        #pragma unroll
        for (int m4 = 0; m4 < 8; m4++) {
            float4 x  = *(const float4*)&bufC[t * S_ + 4*m4];
            float4 mn = *(const float4*)&mean_s[4*m4];
            float4 rs = *(const float4*)&rstd_s[4*m4];
            float v0 = fmaxf((x.x - mn.x) * rs.x * g + b, 0.f);
            float v1 = fmaxf((x.y - mn.y) * rs.y * g + b, 0.f);
            float v2 = fmaxf((x.z - mn.z) * rs.z * g + b, 0.f);
            float v3 = fmaxf((x.w - mn.w) * rs.w * g + b, 0.f);
            int m0 = 4*m4;
            if (n0 + m0     < N_) out[(size_t)(n0 + m0    ) * OUT_ + t] = v0;
            if (n0 + m0 + 1 < N_) out[(size_t)(n0 + m0 + 1) * OUT_ + t] = v1;
            if (n0 + m0 + 2 < N_) out[(size_t)(n0 + m0 + 2) * OUT_ + t] = v2;
            if (n0 + m0 + 3 < N_) out[(size_t)(n0 + m0 + 3) * OUT_ + t] = v3;
        }
    }
}

// ---------------- launch ----------------
extern "C" void kernel_launch(void* const* d_in, const int* in_sizes, int n_in,
                              void* d_out, int out_size) {
    const float* vf     = (const float*)d_in[0];
    const float* coords = (const float*)d_in[1];
    const int*   kidx   = (const int*)  d_in[2];
    const void*  kmask  =               d_in[3];
    const float* ipw    = (const float*)d_in[4];
    const float* ipb    = (const float*)d_in[5];
    const float* opw    = (const float*)d_in[6];
    const float* opb    = (const float*)d_in[7];
    const float* kpw    = (const float*)d_in[8];
    const float* kpb    = (const float*)d_in[9];
    const float* ln1g   = (const float*)d_in[10];
    const float* ln1b   = (const float*)d_in[11];
    const float* ln2g   = (const float*)d_in[12];
    const float* ln2b   = (const float*)d_in[13];
    const float* ff1w   = (const float*)d_in[14];
    const float* ff1b   = (const float*)d_in[15];
    const float* ff2w   = (const float*)d_in[16];
    const float* ff2b   = (const float*)d_in[17];
    const float* outw   = (const float*)d_in[18];
    const float* outb   = (const float*)d_in[19];
    const float* ln3g   = (const float*)d_in[20];
    const float* ln3b   = (const float*)d_in[21];

    kPrep<<<(131072 + 255) / 256, 256>>>(ipw, opw, ff1w, ff2w, outw, (const int*)kmask);
    kA<<<NBLK, 128>>>(vf, ipw, ipb);
    kB<<<N_, 128>>>(vf, coords, kidx, kmask, kpw, kpb);
    kC<<<NBLK, 128>>>(vf, ipb, opb, ln1g, ln1b, ln2g, ln2b,
                      ff1b, ff2b, outb, ln3g, ln3b, (float*)d_out);
}

// round 17
// speedup vs baseline: 1.1416x; 1.1416x over previous
#include <cuda_runtime.h>
#include <cstdint>
#include <cstddef>

#define N_   50000
#define K_   48
#define C_   128
#define H_   8
#define D_   16
#define FF_  256
#define OUT_ 128
#define MT   32
#define S_   36
#define NBLK ((N_ + MT - 1) / MT)

typedef unsigned long long u64;

// ---- f32x2 packed helpers (Blackwell sm_100+) ----
__device__ __forceinline__ u64 pk2(float w) {
    u64 r; asm("mov.b64 %0,{%1,%1};" : "=l"(r) : "f"(w)); return r;
}
__device__ __forceinline__ void f2(u64& d, u64 a, u64 b) {
    asm("fma.rn.f32x2 %0,%1,%2,%0;" : "+l"(d) : "l"(a), "l"(b));
}
__device__ __forceinline__ float2 up2(u64 a) {
    float2 r; asm("mov.b64 {%0,%1},%2;" : "=f"(r.x), "=f"(r.y) : "l"(a)); return r;
}

// ---------------- device scratch ----------------
__device__ float g_QK[(size_t)N_ * H_ * C_];
__device__ float g_QB[(size_t)N_ * H_];
__device__ float g_CTXF[(size_t)N_ * H_ * C_];
__device__ float g_wqT[C_ * C_];
__device__ float g_wvT[C_ * C_];
__device__ float g_opT[C_ * C_];
__device__ float g_ff1T[C_ * FF_];
__device__ float g_ff2T[FF_ * C_];
__device__ float g_outT[C_ * OUT_];
__device__ int   g_mask_is_byte;

// ---------------- weight transposes + mask dtype detect (block 0) ----------------
__global__ void kPrep(const float* __restrict__ ipw, const float* __restrict__ opw,
                      const float* __restrict__ f1w, const float* __restrict__ f2w,
                      const float* __restrict__ ow, const int* __restrict__ km) {
    int i = blockIdx.x * blockDim.x + threadIdx.x;
    if (i < 16384) {
        int e = i >> 7, c = i & 127;
        g_wqT[c * C_ + e] = ipw[e * C_ + c];
    } else if (i < 32768) {
        int j = i - 16384; int e = j >> 7, c = j & 127;
        g_wvT[c * C_ + e] = ipw[(2 * C_ + e) * C_ + c];
    } else if (i < 49152) {
        int j = i - 32768; int e = j >> 7, c = j & 127;
        g_opT[c * C_ + e] = opw[e * C_ + c];
    } else if (i < 81920) {
        int j = i - 49152; int f = j >> 7, c = j & 127;
        g_ff1T[c * FF_ + f] = f1w[f * C_ + c];
    } else if (i < 114688) {
        int j = i - 81920; int e = j >> 8, f = j & 255;
        g_ff2T[f * C_ + e] = f2w[e * FF_ + f];
    } else if (i < 131072) {
        int j = i - 114688; int o = j >> 7, c = j & 127;
        g_outT[c * OUT_ + o] = ow[o * C_ + c];
    }
    if (blockIdx.x == 0) {
        __shared__ int s;
        if (threadIdx.x == 0) s = 0;
        __syncthreads();
        int bad = 0;
        for (int ii = threadIdx.x; ii < 4096; ii += 256)
            if (((unsigned)km[ii]) > 1u) bad = 1;
        if (bad) atomicOr(&s, 1);
        __syncthreads();
        if (threadIdx.x == 0) g_mask_is_byte = s;
    }
}

// ---- tiled-GEMM helpers: thread covers ch = ch0..ch0+3, m = mg8..mg8+7 ----
#define ZACC(A) do { _Pragma("unroll") for (int j_=0;j_<4;j_++) { \
    _Pragma("unroll") for (int p_=0;p_<4;p_++) (A)[j_][p_] = 0; } } while (0)

#define G2STEP(BUF, ROW, W4, ACC) do {                                          \
    ulonglong2 x01_ = *(const ulonglong2*)&(BUF)[(ROW)*S_ + mg8];               \
    ulonglong2 x23_ = *(const ulonglong2*)&(BUF)[(ROW)*S_ + mg8 + 4];           \
    u64 w0_=pk2((W4).x), w1_=pk2((W4).y), w2_=pk2((W4).z), w3_=pk2((W4).w);     \
    f2((ACC)[0][0],x01_.x,w0_); f2((ACC)[0][1],x01_.y,w0_);                     \
    f2((ACC)[0][2],x23_.x,w0_); f2((ACC)[0][3],x23_.y,w0_);                     \
    f2((ACC)[1][0],x01_.x,w1_); f2((ACC)[1][1],x01_.y,w1_);                     \
    f2((ACC)[1][2],x23_.x,w1_); f2((ACC)[1][3],x23_.y,w1_);                     \
    f2((ACC)[2][0],x01_.x,w2_); f2((ACC)[2][1],x01_.y,w2_);                     \
    f2((ACC)[2][2],x23_.x,w2_); f2((ACC)[2][3],x23_.y,w2_);                     \
    f2((ACC)[3][0],x01_.x,w3_); f2((ACC)[3][1],x01_.y,w3_);                     \
    f2((ACC)[3][2],x23_.x,w3_); f2((ACC)[3][3],x23_.y,w3_);                     \
} while (0)

#define STORE4(BUF, ACC, B4PTR, RELU) do {                                      \
    float4 b4_ = (B4PTR)[og];                                                   \
    float bj_[4] = {b4_.x, b4_.y, b4_.z, b4_.w};                                \
    _Pragma("unroll") for (int j_=0;j_<4;j_++) {                                \
      _Pragma("unroll") for (int p_=0;p_<4;p_++) {                              \
        float2 s_ = up2((ACC)[j_][p_]);                                         \
        s_.x += bj_[j_]; s_.y += bj_[j_];                                       \
        if (RELU) { s_.x = fmaxf(s_.x, 0.f); s_.y = fmaxf(s_.y, 0.f); }         \
        *(float2*)&(BUF)[(ch0+j_)*S_ + mg8 + 2*p_] = s_;                        \
      } }                                                                       \
} while (0)

// vectorized LN apply: x = (x - mean)*rstd*g + b over m = 0..31 (float4)
#define LNAPPLY(BUF, GV, BV) do {                                               \
    float g_ = (GV), b_ = (BV);                                                 \
    _Pragma("unroll")                                                           \
    for (int m4_ = 0; m4_ < 8; m4_++) {                                         \
        float4 x_  = *(float4*)&(BUF)[t * S_ + 4*m4_];                          \
        float4 mn_ = *(const float4*)&mean_s[4*m4_];                            \
        float4 rs_ = *(const float4*)&rstd_s[4*m4_];                            \
        x_.x = (x_.x - mn_.x) * rs_.x * g_ + b_;                                \
        x_.y = (x_.y - mn_.y) * rs_.y * g_ + b_;                                \
        x_.z = (x_.z - mn_.z) * rs_.z * g_ + b_;                                \
        x_.w = (x_.w - mn_.w) * rs_.w * g_ + b_;                                \
        *(float4*)&(BUF)[t * S_ + 4*m4_] = x_;                                  \
    } } while (0)

// ---------------- kernel A ----------------
__global__ void __launch_bounds__(128) kA(const float* __restrict__ vf,
                                          const float* __restrict__ ipw,
                                          const float* __restrict__ ipb) {
    __shared__ float vsT[C_ * S_];
    __shared__ float QsT[C_ * S_];
    int t = threadIdx.x;
    int n0 = blockIdx.x * MT;
    int mg = t & 3, og = t >> 2;
    int mg8 = mg * 8, ch0 = og * 4;

    #pragma unroll
    for (int m4 = 0; m4 < 8; m4++) {
        float a[4];
        #pragma unroll
        for (int j = 0; j < 4; j++) {
            int n = n0 + 4*m4 + j; if (n >= N_) n = N_ - 1;
            a[j] = vf[(size_t)n * C_ + t];
        }
        *(float4*)&vsT[t * S_ + 4*m4] = make_float4(a[0], a[1], a[2], a[3]);
    }
    __syncthreads();

    u64 acc[4][4];
    ZACC(acc);
    for (int c = 0; c < C_; c++) {
        float4 w4 = *(const float4*)&g_wqT[c * C_ + ch0];
        G2STEP(vsT, c, w4, acc);
    }
    STORE4(QsT, acc, (const float4*)ipb, false);
    __syncthreads();

    for (int h = 0; h < H_; h++) {
        ZACC(acc);
        #pragma unroll
        for (int d = 0; d < D_; d++) {
            int e = h * D_ + d;
            float4 w4 = *(const float4*)&ipw[(size_t)(C_ + e) * C_ + ch0];
            G2STEP(QsT, e, w4, acc);
        }
        #pragma unroll
        for (int j = 0; j < 4; j++)
            #pragma unroll
            for (int p = 0; p < 4; p++) {
                float2 s = up2(acc[j][p]);
                int m0 = mg8 + 2*p;
                int na = n0 + m0, nb = n0 + m0 + 1;
                if (na < N_) g_QK[(size_t)na * (H_*C_) + h * C_ + ch0 + j] = s.x;
                if (nb < N_) g_QK[(size_t)nb * (H_*C_) + h * C_ + ch0 + j] = s.y;
            }
    }
    if (t < MT) {
        int n = n0 + t;
        if (n < N_) {
            for (int h = 0; h < H_; h++) {
                float s = 0.f;
                for (int d = 0; d < D_; d++) {
                    int e = h * D_ + d;
                    s = fmaf(QsT[e * S_ + t], ipb[C_ + e], s);
                }
                g_QB[(size_t)n * H_ + h] = s;
            }
        }
    }
}

// ---------------- kernel B (R9 best: qk4 staging, 32-lane fused softmax scores, 2-warp ctxfeat) ----------------
__global__ void __launch_bounds__(128) kB(const float* __restrict__ vf,
                                          const float* __restrict__ coords,
                                          const int* __restrict__ kidx,
                                          const void* __restrict__ kmask,
                                          const float* __restrict__ kpw,
                                          const float* __restrict__ kpb) {
    __shared__ float4 kf4[K_ * 33];
    __shared__ float4 qk4[H_ * 33];
    __shared__ __align__(16) float attnS[K_ * 8];      // [k*8 + h]
    __shared__ int   idxs[K_];
    __shared__ float relx[K_], rely[K_], relz[K_];
    __shared__ float qb_s[H_];
    __shared__ unsigned char msk[K_];

    int t = threadIdx.x;
    int n = blockIdx.x;
    int isbyte = g_mask_is_byte;

    if (t < K_) {
        int i = kidx[(size_t)n * K_ + t];
        idxs[t] = i;
        unsigned char mk;
        if (isbyte) mk = (((const unsigned char*)kmask)[(size_t)n * K_ + t] != 0);
        else        mk = (((const int*)kmask)[(size_t)n * K_ + t] != 0);
        msk[t] = mk;
        relx[t] = coords[(size_t)i * 3 + 0] - coords[(size_t)n * 3 + 0];
        rely[t] = coords[(size_t)i * 3 + 1] - coords[(size_t)n * 3 + 1];
        relz[t] = coords[(size_t)i * 3 + 2] - coords[(size_t)n * 3 + 2];
    }
    if (t < H_) qb_s[t] = g_QB[(size_t)n * H_ + t];
    {
        int h = t >> 4, c2 = (t & 15) * 2;
        const float4* src = (const float4*)(g_QK + (size_t)n * (H_ * C_) + h * C_);
        qk4[h * 33 + c2]     = __ldg(src + c2);
        qk4[h * 33 + c2 + 1] = __ldg(src + c2 + 1);
    }

    int c4 = t & 31, q = t >> 5;
    float4 wa = __ldg((const float4*)(kpw + 12 * c4));
    float4 wb = __ldg((const float4*)(kpw + 12 * c4 + 4));
    float4 wc = __ldg((const float4*)(kpw + 12 * c4 + 8));
    float4 pb4 = __ldg((const float4*)(kpb + 4 * c4));
    __syncthreads();

    // gather + posemb: 4 channels x 12 keys per thread
    #pragma unroll
    for (int kk = 0; kk < 12; kk++) {
        int k = q * 12 + kk;
        int i = idxs[k];
        float4 v = __ldg((const float4*)(vf + (size_t)i * C_) + c4);
        float rx = relx[k], ry = rely[k], rz = relz[k];
        float p0 = fmaf(rz, wa.z, fmaf(ry, wa.y, fmaf(rx, wa.x, pb4.x)));
        float p1 = fmaf(rz, wb.y, fmaf(ry, wb.x, fmaf(rx, wa.w, pb4.y)));
        float p2 = fmaf(rz, wc.x, fmaf(ry, wb.w, fmaf(rx, wb.z, pb4.z)));
        float p3 = fmaf(rz, wc.w, fmaf(ry, wc.z, fmaf(rx, wc.y, pb4.w)));
        v.x += fmaxf(p0, 0.f); v.y += fmaxf(p1, 0.f);
        v.z += fmaxf(p2, 0.f); v.w += fmaxf(p3, 0.f);
        kf4[k * 33 + c4] = v;
    }
    __syncthreads();

    // scores + fused softmax: one warp
    // thread (g = t&1, kp = t>>1) -> keys {kp, kp+16, kp+32}, heads 4g..4g+3
    if (t < 32) {
        int g  = t & 1;
        int kp = t >> 1;
        u64 a[3][4];
        #pragma unroll
        for (int kk = 0; kk < 3; kk++)
            #pragma unroll
            for (int j = 0; j < 4; j++) a[kk][j] = 0;
        #pragma unroll 4
        for (int c = 0; c < 32; c++) {
            ulonglong2 f0 = *(const ulonglong2*)&kf4[kp * 33 + c];
            ulonglong2 f1 = *(const ulonglong2*)&kf4[(kp + 16) * 33 + c];
            ulonglong2 fv = *(const ulonglong2*)&kf4[(kp + 32) * 33 + c];
            #pragma unroll
            for (int j = 0; j < 4; j++) {
                ulonglong2 qv = *(const ulonglong2*)&qk4[(4 * g + j) * 33 + c];
                f2(a[0][j], f0.x, qv.x); f2(a[0][j], f0.y, qv.y);
                f2(a[1][j], f1.x, qv.x); f2(a[1][j], f1.y, qv.y);
                f2(a[2][j], fv.x, qv.x); f2(a[2][j], fv.y, qv.y);
            }
        }
        float sc[3][4];
        #pragma unroll
        for (int kk = 0; kk < 3; kk++) {
            int k = kp + 16 * kk;
            bool mk = msk[k] != 0;
            #pragma unroll
            for (int j = 0; j < 4; j++) {
                float2 s = up2(a[kk][j]);
                float val = (s.x + s.y + qb_s[4 * g + j]) * 0.25f;
                sc[kk][j] = mk ? -1e9f : val;
            }
        }
        // softmax per head across the 16 same-parity lanes (offsets 2,4,8,16 preserve t&1)
        #pragma unroll
        for (int j = 0; j < 4; j++) {
            float mx = fmaxf(sc[0][j], fmaxf(sc[1][j], sc[2][j]));
            #pragma unroll
            for (int o = 2; o < 32; o <<= 1)
                mx = fmaxf(mx, __shfl_xor_sync(0xffffffffu, mx, o));
            float e0 = __expf(sc[0][j] - mx);
            float e1 = __expf(sc[1][j] - mx);
            float e2 = __expf(sc[2][j] - mx);
            float sm = e0 + e1 + e2;
            #pragma unroll
            for (int o = 2; o < 32; o <<= 1)
                sm += __shfl_xor_sync(0xffffffffu, sm, o);
            float inv = 1.f / sm;
            sc[0][j] = e0 * inv; sc[1][j] = e1 * inv; sc[2][j] = e2 * inv;
        }
        #pragma unroll
        for (int kk = 0; kk < 3; kk++)
            *(float4*)&attnS[(kp + 16 * kk) * 8 + 4 * g] =
                make_float4(sc[kk][0], sc[kk][1], sc[kk][2], sc[kk][3]);
    }
    __syncthreads();

    // ctxfeat: 2 warps; warp w -> heads 4w..4w+3, lane -> float4 column
    if (t < 64) {
        int w = t >> 5, cc = t & 31;
        u64 A[4][2];
        #pragma unroll
        for (int j = 0; j < 4; j++) { A[j][0] = 0; A[j][1] = 0; }
        #pragma unroll 4
        for (int k = 0; k < K_; k++) {
            ulonglong2 f = *(const ulonglong2*)&kf4[k * 33 + cc];
            float4 a4 = *(const float4*)&attnS[k * 8 + 4 * w];
            u64 a0 = pk2(a4.x), a1 = pk2(a4.y), a2 = pk2(a4.z), a3 = pk2(a4.w);
            f2(A[0][0], f.x, a0); f2(A[0][1], f.y, a0);
            f2(A[1][0], f.x, a1); f2(A[1][1], f.y, a1);
            f2(A[2][0], f.x, a2); f2(A[2][1], f.y, a2);
            f2(A[3][0], f.x, a3); f2(A[3][1], f.y, a3);
        }
        float4* dst = (float4*)(g_CTXF + (size_t)n * (H_ * C_));
        #pragma unroll
        for (int j = 0; j < 4; j++) {
            float2 xy = up2(A[j][0]);
            float2 zw = up2(A[j][1]);
            dst[(4 * w + j) * 32 + cc] = make_float4(xy.x, xy.y, zw.x, zw.y);
        }
    }
}

// ---------------- kernel C (R14: vectorized elementwise phases) ----------------
__global__ void __launch_bounds__(128) kC(const float* __restrict__ vf,
                                          const float* __restrict__ ipb,
                                          const float* __restrict__ opb,
                                          const float* __restrict__ ln1g, const float* __restrict__ ln1b,
                                          const float* __restrict__ ln2g, const float* __restrict__ ln2b,
                                          const float* __restrict__ ff1b, const float* __restrict__ ff2b,
                                          const float* __restrict__ outb,
                                          const float* __restrict__ ln3g, const float* __restrict__ ln3b,
                                          float* __restrict__ out) {
    __shared__ float bufA[C_ * S_];
    __shared__ float bufC[C_ * S_];
    __shared__ __align__(16) float mean_s[MT];
    __shared__ __align__(16) float rstd_s[MT];

    int t = threadIdx.x;
    int n0 = blockIdx.x * MT;
    int mg = t & 3, og = t >> 2;
    int mg8 = mg * 8, ch0 = og * 4;

    u64 acc[4][4];
    ZACC(acc);

    // --- ctx: staged ctxfeat chunks (8 x 16 cols, sequential) ---
    int rb = (og >> 2) * 16;
    for (int ch = 0; ch < 8; ch++) {
        int c0 = ch * 16;
        __syncthreads();
        {
            int hh = t >> 4, cl = t & 15;
            #pragma unroll
            for (int m4 = 0; m4 < 8; m4++) {
                float a[4];
                #pragma unroll
                for (int j = 0; j < 4; j++) {
                    int n = n0 + 4*m4 + j; if (n >= N_) n = N_ - 1;
                    a[j] = g_CTXF[(size_t)n * (H_*C_) + hh * C_ + c0 + cl];
                }
                *(float4*)&bufC[t * S_ + 4*m4] = make_float4(a[0], a[1], a[2], a[3]);
            }
        }
        __syncthreads();
        #pragma unroll
        for (int cl = 0; cl < 16; cl++) {
            float4 w4 = *(const float4*)&g_wvT[(c0 + cl) * C_ + ch0];
            G2STEP(bufC, rb + cl, w4, acc);
        }
    }
    __syncthreads();
    STORE4(bufC, acc, (const float4*)(ipb + 2 * C_), false);
    __syncthreads();

    // --- attend ---
    ZACC(acc);
    for (int c = 0; c < C_; c++) {
        float4 w4 = *(const float4*)&g_opT[c * C_ + ch0];
        G2STEP(bufC, c, w4, acc);
    }
    __syncthreads();
    STORE4(bufA, acc, (const float4*)opb, false);
    __syncthreads();
    // residual (coalesced LDG, vectorized smem)
    #pragma unroll
    for (int m4 = 0; m4 < 8; m4++) {
        float4 x = *(float4*)&bufA[t * S_ + 4*m4];
        float r[4];
        #pragma unroll
        for (int j = 0; j < 4; j++) {
            int n = n0 + 4*m4 + j; if (n >= N_) n = N_ - 1;
            r[j] = vf[(size_t)n * C_ + t];
        }
        x.x += r[0]; x.y += r[1]; x.z += r[2]; x.w += r[3];
        *(float4*)&bufA[t * S_ + 4*m4] = x;
    }
    __syncthreads();
    if (t < MT) {
        float s = 0.f, s2 = 0.f;
        for (int c = 0; c < C_; c++) { float v = bufA[c * S_ + t]; s += v; s2 = fmaf(v, v, s2); }
        float mn = s * (1.f / C_);
        mean_s[t] = mn; rstd_s[t] = rsqrtf(s2 * (1.f / C_) - mn * mn + 1e-5f);
    }
    __syncthreads();
    LNAPPLY(bufA, ln1g[t], ln1b[t]);
    __syncthreads();

    // --- FF ---
    u64 acc2[4][4];
    ZACC(acc2);
    for (int fc = 0; fc < 2; fc++) {
        ZACC(acc);
        for (int c = 0; c < C_; c++) {
            float4 w4 = *(const float4*)&g_ff1T[c * FF_ + fc * 128 + ch0];
            G2STEP(bufA, c, w4, acc);
        }
        __syncthreads();
        STORE4(bufC, acc, (const float4*)(ff1b + fc * 128), true);
        __syncthreads();
        for (int fl = 0; fl < 128; fl++) {
            float4 w4 = *(const float4*)&g_ff2T[(size_t)(fc * 128 + fl) * C_ + ch0];
            G2STEP(bufC, fl, w4, acc2);
        }
    }
    __syncthreads();
    STORE4(bufC, acc2, (const float4*)ff2b, false);
    __syncthreads();
    // x2 = x1 + ff (vectorized)
    #pragma unroll
    for (int m4 = 0; m4 < 8; m4++) {
        float4 x = *(float4*)&bufA[t * S_ + 4*m4];
        float4 y = *(const float4*)&bufC[t * S_ + 4*m4];
        x.x += y.x; x.y += y.y; x.z += y.z; x.w += y.w;
        *(float4*)&bufA[t * S_ + 4*m4] = x;
    }
    __syncthreads();
    if (t < MT) {
        float s = 0.f, s2 = 0.f;
        for (int c = 0; c < C_; c++) { float v = bufA[c * S_ + t]; s += v; s2 = fmaf(v, v, s2); }
        float mn = s * (1.f / C_);
        mean_s[t] = mn; rstd_s[t] = rsqrtf(s2 * (1.f / C_) - mn * mn + 1e-5f);
    }
    __syncthreads();
    LNAPPLY(bufA, ln2g[t], ln2b[t]);
    __syncthreads();

    // --- out projection ---
    ZACC(acc);
    for (int c = 0; c < C_; c++) {
        float4 w4 = *(const float4*)&g_outT[c * OUT_ + ch0];
        G2STEP(bufA, c, w4, acc);
    }
    __syncthreads();
    STORE4(bufC, acc, (const float4*)outb, false);
    __syncthreads();
    if (t < MT) {
        float s = 0.f, s2 = 0.f;
        for (int c = 0; c < OUT_; c++) { float v = bufC[c * S_ + t]; s += v; s2 = fmaf(v, v, s2); }
        float mn = s * (1.f / OUT_);
        mean_s[t] = mn; rstd_s[t] = rsqrtf(s2 * (1.f / OUT_) - mn * mn + 1e-5f);
    }
    __syncthreads();
    {
        float g = ln3g[t], b = ln3b[t];
        #pragma unroll
        for (int m4 = 0; m4 < 8; m4++) {
            float4 x  = *(const float4*)&bufC[t * S_ + 4*m4];
            float4 mn = *(const float4*)&mean_s[4*m4];
            float4 rs = *(const float4*)&rstd_s[4*m4];
            float v0 = fmaxf((x.x - mn.x) * rs.x * g + b, 0.f);
            float v1 = fmaxf((x.y - mn.y) * rs.y * g + b, 0.f);
            float v2 = fmaxf((x.z - mn.z) * rs.z * g + b, 0.f);
            float v3 = fmaxf((x.w - mn.w) * rs.w * g + b, 0.f);
            int m0 = 4*m4;
            if (n0 + m0     < N_) out[(size_t)(n0 + m0    ) * OUT_ + t] = v0;
            if (n0 + m0 + 1 < N_) out[(size_t)(n0 + m0 + 1) * OUT_ + t] = v1;
            if (n0 + m0 + 2 < N_) out[(size_t)(n0 + m0 + 2) * OUT_ + t] = v2;
            if (n0 + m0 + 3 < N_) out[(size_t)(n0 + m0 + 3) * OUT_ + t] = v3;
        }
    }
}

// ---------------- launch ----------------
extern "C" void kernel_launch(void* const* d_in, const int* in_sizes, int n_in,
                              void* d_out, int out_size) {
    const float* vf     = (const float*)d_in[0];
    const float* coords = (const float*)d_in[1];
    const int*   kidx   = (const int*)  d_in[2];
    const void*  kmask  =               d_in[3];
    const float* ipw    = (const float*)d_in[4];
    const float* ipb    = (const float*)d_in[5];
    const float* opw    = (const float*)d_in[6];
    const float* opb    = (const float*)d_in[7];
    const float* kpw    = (const float*)d_in[8];
    const float* kpb    = (const float*)d_in[9];
    const float* ln1g   = (const float*)d_in[10];
    const float* ln1b   = (const float*)d_in[11];
    const float* ln2g   = (const float*)d_in[12];
    const float* ln2b   = (const float*)d_in[13];
    const float* ff1w   = (const float*)d_in[14];
    const float* ff1b   = (const float*)d_in[15];
    const float* ff2w   = (const float*)d_in[16];
    const float* ff2b   = (const float*)d_in[17];
    const float* outw   = (const float*)d_in[18];
    const float* outb   = (const float*)d_in[19];
    const float* ln3g   = (const float*)d_in[20];
    const float* ln3b   = (const float*)d_in[21];

    kPrep<<<(131072 + 255) / 256, 256>>>(ipw, opw, ff1w, ff2w, outw, (const int*)kmask);
    kA<<<NBLK, 128>>>(vf, ipw, ipb);
    kB<<<N_, 128>>>(vf, coords, kidx, kmask, kpw, kpb);
    kC<<<NBLK, 128>>>(vf, ipb, opb, ln1g, ln1b, ln2g, ln2b,
                      ff1b, ff2b, outb, ln3g, ln3b, (float*)d_out);
}